// round 1
// baseline (speedup 1.0000x reference)
#include <cuda_runtime.h>
#include <cuda_bf16.h>
#include <cstdint>

// SimplifiedMambaBlock: the reference scan has no input term into the state
//   h0 = 0;  h = exp(dt*A) * h;  y = h.sum(-1) * C
// so h == 0 forever (exp(dt*A) is finite, 0 * finite = 0), ssm_out == 0,
// y = 0 * silu(z) == 0, out_proj @ 0 == 0, and out = residual = x bit-exactly.
// The whole block is the identity on x. Fastest correct kernel: copy x -> out.

__global__ void __launch_bounds__(256) identity_copy_f4(
    const float4* __restrict__ src, float4* __restrict__ dst, long n4)
{
    long i = (long)blockIdx.x * blockDim.x + threadIdx.x;
    long stride = (long)gridDim.x * blockDim.x;
    // grid-stride with 16B vectors; 2 iterations per thread at this config
    for (; i < n4; i += stride) {
        dst[i] = src[i];
    }
}

extern "C" void kernel_launch(void* const* d_in, const int* in_sizes, int n_in,
                              void* d_out, int out_size) {
    const float* x = (const float*)d_in[0];   // (8, 2048, 512) float32
    float* out = (float*)d_out;               // same shape

    long n = (long)in_sizes[0];               // 8*2048*512 = 8,388,608 (divisible by 4)
    long n4 = n / 4;                          // 2,097,152 float4

    // 4096 blocks * 256 threads = 1,048,576 threads -> 2 float4 per thread.
    // Enough CTAs for all 148 SMs with deep MLP per warp.
    int threads = 256;
    int blocks = 4096;
    identity_copy_f4<<<blocks, threads>>>(
        (const float4*)x, (float4*)out, n4);
}